// round 6
// baseline (speedup 1.0000x reference)
#include <cuda_runtime.h>

#define BIGV 10000000000.0f
#define L2E  1.4426950408889634f
#define LN2  0.6931471805599453f

typedef unsigned long long u64;

__device__ __forceinline__ float ex2f_(float x){ float r; asm("ex2.approx.f32 %0, %1;" : "=f"(r) : "f"(x)); return r; }
__device__ __forceinline__ float lg2f_(float x){ float r; asm("lg2.approx.f32 %0, %1;" : "=f"(r) : "f"(x)); return r; }
__device__ __forceinline__ u64 pk2(float lo, float hi){ u64 r; asm("mov.b64 %0,{%1,%2};" : "=l"(r) : "f"(lo), "f"(hi)); return r; }
__device__ __forceinline__ void upk2(float& lo, float& hi, u64 v){ asm("mov.b64 {%0,%1},%2;" : "=f"(lo), "=f"(hi) : "l"(v)); }
__device__ __forceinline__ u64 fma2(u64 a, u64 b, u64 c){ u64 r; asm("fma.rn.f32x2 %0,%1,%2,%3;" : "=l"(r) : "l"(a), "l"(b), "l"(c)); return r; }

// One warp = two (a,b) pairs fused in anti-phase (+128 steps), 4 rows/thread.
// DP carried as V = g - lg2(e): exp-split softmin, renorm every OTHER step
// (e in [1,6) on skip steps, split exact for any ss>=1). Renorm uses the
// integer->float magic-number trick (no I2F on the critical chain).
__global__ __launch_bounds__(128)
void sdtw_kernel(const float* __restrict__ X, const float* __restrict__ Y,
                 float* __restrict__ out)
{
    // row j of tile t: 8 floats in two 16B chunks:
    //   sy[t*1152 + (j&3)*256 + q*128 + ((j>>2))*4 + c] = Y[j][4q+c]
    // sqy (L2E-scaled): sy[t*1152 + 1024 + (j&3)*32 + (j>>2)]
    __shared__ __align__(16) float sy[2 * 1152];

    const int tid  = threadIdx.x;
    const int lane = tid & 31;
    const int wid  = tid >> 5;

    const int b0 = (blockIdx.x & 7) * 2;
    const int a  = (blockIdx.x >> 3) * 4 + wid;

    for (int rep = 0; rep < 2; ++rep) {
        int gr   = tid + rep * 128;
        int tile = gr >> 7;
        int j    = gr & 127;
        const float* yrow = Y + (size_t)(b0 + tile) * 1024 + j * 8;
        float sq = 0.f;
        int base = tile * 1152 + (j & 3) * 256 + (j >> 2) * 4;
        #pragma unroll
        for (int k = 0; k < 8; ++k) {
            float vv = yrow[k];
            sq = fmaf(vv, vv, sq);
            sy[base + (k >> 2) * 128 + (k & 3)] = vv;
        }
        sy[tile * 1152 + 1024 + (j & 3) * 32 + (j >> 2)] = sq * L2E;
    }

    // X: packed xs2 = -2*L2E*x (pairs (2k,2k+1)); sqx = L2E*|x|^2 (unbiased)
    u64   xs2[4][4];
    float sqx[4];
    {
        const float* xp = X + (size_t)a * 1024 + lane * 32;
        #pragma unroll
        for (int s = 0; s < 4; ++s) {
            float acc = 0.f;
            #pragma unroll
            for (int kp = 0; kp < 4; ++kp) {
                float f0 = xp[s * 8 + 2 * kp];
                float f1 = xp[s * 8 + 2 * kp + 1];
                acc = fmaf(f0, f0, fmaf(f1, f1, acc));
                xs2[s][kp] = pk2(f0 * (-2.0f * L2E), f1 * (-2.0f * L2E));
            }
            sqx[s] = acc * L2E;
        }
    }
    __syncthreads();

    float g[2][4], e[2][4];
    #pragma unroll
    for (int s = 0; s < 4; ++s) {
        g[0][s] = BIGV; g[1][s] = BIGV;
        e[0][s] = 1.0f; e[1][s] = 1.0f;
    }

    // Y register pipeline: buffer (p)&3 holds row ja0(p) = p - 4*lane; refilled at
    // the END of step p-? (after slot 3, its last same-step reader, has consumed it).
    u64   yp2[4][4];
    float yq[4];
    #pragma unroll
    for (int q = 0; q < 4; ++q) {
        yq[q] = 0.f;
        #pragma unroll
        for (int kp = 0; kp < 4; ++kp) yp2[q][kp] = 0ull;
    }

    const int lane4 = lane * 4;

    // prologue: buffer 0 <- row ja0(p=0) = -lane4 (wrapped; real only for lane 0)
    {
        unsigned jb = (unsigned)(-lane4) & 255u;
        int t   = (int)(jb >> 7) * 1152;
        int off = (int)((jb >> 2) & 31u);
        int A   = t + (int)(jb & 3u) * 256 + off * 4;
        float4 c0 = *reinterpret_cast<const float4*>(&sy[A]);
        float4 c1 = *reinterpret_cast<const float4*>(&sy[A + 128]);
        yp2[0][0] = pk2(c0.x, c0.y); yp2[0][1] = pk2(c0.z, c0.w);
        yp2[0][2] = pk2(c1.x, c1.y); yp2[0][3] = pk2(c1.z, c1.w);
        yq[0] = sy[t + 1024 + (int)(jb & 3u) * 32 + off];
    }

    float shPg = BIGV, shPe = 1.0f;
    const int outA = a * 16 + b0;

    for (int p0 = 0; p0 < 384; p0 += 4) {
        const int j0      = p0 - lane4;
        const unsigned jc = (unsigned)j0 & 255u;
        const unsigned jn = (unsigned)(j0 + 4) & 255u;
        const int tOff0   = (int)(jc >> 7) * 1152;
        const int m0      = (int)((jc >> 2) & 31u);
        const int baseY0  = tOff0 + m0 * 4;          // + u*256 (+128 for chunk 1)
        const int qb0     = tOff0 + 1024 + m0;       // + u*32
        const int tOff1   = (int)(jn >> 7) * 1152;
        const int m1      = (int)((jn >> 2) & 31u);
        const int baseY1  = tOff1 + m1 * 4;
        const int qb1     = tOff1 + 1024 + m1;
        const bool bj0    = ((jc & 127u) == 0u);     // j==0 boundary fires only at cells s==u

        #pragma unroll
        for (int u = 0; u < 4; ++u) {
            const int wIdx = u & 1;
            const int rIdx = wIdx ^ 1;

            const float sh1g = __shfl_up_sync(0xffffffffu, g[rIdx][3], 1);
            const float sh1e = __shfl_up_sync(0xffffffffu, e[rIdx][3], 1);

            // reverse slot order: slot s reads g[wIdx][s-1] (prev2) before slot s-1 writes it
            #pragma unroll
            for (int s = 3; s >= 0; --s) {
                float gu, gl, gd, eu, el, ed;
                if (s == 0) {
                    gu = (lane == 0) ? BIGV : sh1g;  eu = sh1e;
                    if (u == 0) {
                        gl = bj0 ? BIGV : g[rIdx][0];  el = e[rIdx][0];
                        if (lane == 0) { gd = bj0 ? 0.0f : BIGV;  ed = 1.0f; }
                        else           { gd = bj0 ? BIGV : shPg;  ed = shPe; }
                    } else {
                        gl = g[rIdx][0];                el = e[rIdx][0];
                        gd = (lane == 0) ? BIGV : shPg; ed = shPe;
                    }
                } else {
                    gu = g[rIdx][s - 1];  eu = e[rIdx][s - 1];
                    if (s == u) {
                        gl = bj0 ? BIGV : g[rIdx][s];      el = e[rIdx][s];
                        gd = bj0 ? BIGV : g[wIdx][s - 1];  ed = e[wIdx][s - 1];
                    } else {
                        gl = g[rIdx][s];      el = e[rIdx][s];
                        gd = g[wIdx][s - 1];  ed = e[wIdx][s - 1];
                    }
                }

                // exp-split softmin: shift by exact min of g; min term contributes e_i >= 1
                float m  = fminf(fminf(gu, gl), gd);
                float ss = fmaf(eu, ex2f_(m - gu),
                           fmaf(el, ex2f_(m - gl), ed * ex2f_(m - gd)));   // ss >= 1

                // d' = L2E*|x-y|^2 via packed FMAs
                u64 acc2 = pk2(sqx[s], yq[(u - s) & 3]);
                #pragma unroll
                for (int kp = 0; kp < 4; ++kp)
                    acc2 = fma2(xs2[s][kp], yp2[(u - s) & 3][kp], acc2);
                float lo, hi; upk2(lo, hi, acc2);
                float dsum = lo + hi;

                if ((u & 1) == 0) {
                    // renorm step: exact exponent split, magic-number int->float
                    unsigned ub = __float_as_uint(ss);
                    float kff = __uint_as_float((ub >> 23) | 0x4B000000u) - 8388735.0f; // = k
                    e[wIdx][s] = __uint_as_float((ub & 0x007FFFFFu) | 0x3F800000u);     // [1,2)
                    g[wIdx][s] = dsum + (m - kff);
                } else {
                    // skip step: carry e unnormalized (< 6); bounded, exact
                    e[wIdx][s] = ss;
                    g[wIdx][s] = dsum + m;
                }
            }

            // refill buffer (u+1)&3 with row j0+u+1 AFTER its last reader (slot 3) is done
            {
                const int A  = (u < 3) ? (baseY0 + (u + 1) * 256) : baseY1;
                const int b  = (u + 1) & 3;
                float4 c0 = *reinterpret_cast<const float4*>(&sy[A]);
                float4 c1 = *reinterpret_cast<const float4*>(&sy[A + 128]);
                yp2[b][0] = pk2(c0.x, c0.y); yp2[b][1] = pk2(c0.z, c0.w);
                yp2[b][2] = pk2(c1.x, c1.y); yp2[b][3] = pk2(c1.z, c1.w);
                yq[b] = (u < 3) ? sy[qb0 + (u + 1) * 32] : sy[qb1];
            }

            // harvest: pair A at p=254 (p0=252,u=2), pair B at p=382 (p0=380,u=2)
            if (u == 2 && lane == 31) {
                if (p0 == 252) out[outA]     = (g[0][3] - lg2f_(e[0][3])) * LN2;
                if (p0 == 380) out[outA + 1] = (g[0][3] - lg2f_(e[0][3])) * LN2;
            }

            shPg = sh1g;
            shPe = sh1e;
        }
    }
}

extern "C" void kernel_launch(void* const* d_in, const int* in_sizes, int n_in,
                              void* d_out, int out_size)
{
    const float* X = (const float*)d_in[0];
    const float* Y = (const float*)d_in[1];
    if (n_in >= 2 && in_sizes[0] < in_sizes[1]) {
        const float* t = X; X = Y; Y = t;
    }
    float* out = (float*)d_out;

    sdtw_kernel<<<256, 128>>>(X, Y, out);
}

// round 7
// speedup vs baseline: 1.1163x; 1.1163x over previous
#include <cuda_runtime.h>

#define L2E  1.4426950408889634f
#define LN2  0.6931471805599453f
#define BIGQ (-(1 << 27))

typedef unsigned long long u64;

__device__ __forceinline__ float ex2f_(float x){ float r; asm("ex2.approx.f32 %0, %1;" : "=f"(r) : "f"(x)); return r; }
__device__ __forceinline__ float lg2f_(float x){ float r; asm("lg2.approx.f32 %0, %1;" : "=f"(r) : "f"(x)); return r; }
__device__ __forceinline__ u64 pk2(float lo, float hi){ u64 r; asm("mov.b64 %0,{%1,%2};" : "=l"(r) : "f"(lo), "f"(hi)); return r; }
__device__ __forceinline__ void upk2(float& lo, float& hi, u64 v){ asm("mov.b64 {%0,%1},%2;" : "=f"(lo), "=f"(hi) : "l"(v)); }
__device__ __forceinline__ u64 fma2(u64 a, u64 b, u64 c){ u64 r; asm("fma.rn.f32x2 %0,%1,%2,%3;" : "=l"(r) : "l"(a), "l"(b), "l"(c)); return r; }

// exact e * 2^max(dq, -126), e in [1,2), dq <= 0  (pure ALU, no MUFU)
__device__ __forceinline__ float scl_(float e, int dq){
    int d = dq < -126 ? -126 : dq;
    return __uint_as_float(__float_as_uint(e) + ((unsigned)d << 23));
}

// One warp = two (a,b) pairs fused in anti-phase (+128 steps), 4 rows/thread.
// DP carried in WEIGHT domain: w = e * 2^q  (e float in [1,2), q int32).
// softmin = aligned add (exponent-bit arithmetic, no MUFU on the carried chain);
// the single ex2 per cell takes the distance term, which is neighbor-independent.
__global__ __launch_bounds__(128)
void sdtw_kernel(const float* __restrict__ X, const float* __restrict__ Y,
                 float* __restrict__ out)
{
    // row j of tile t: sy[t*1152 + (j&3)*256 + q*128 + (j>>2)*4 + c] = Y[j][4q+c]
    // nsqy = -L2E*|Y[j]|^2 at sy[t*1152 + 1024 + (j&3)*32 + (j>>2)]
    __shared__ __align__(16) float sy[2 * 1152];

    const int tid  = threadIdx.x;
    const int lane = tid & 31;
    const int wid  = tid >> 5;

    const int b0 = (blockIdx.x & 7) * 2;
    const int a  = (blockIdx.x >> 3) * 4 + wid;

    for (int rep = 0; rep < 2; ++rep) {
        int gr   = tid + rep * 128;
        int tile = gr >> 7;
        int j    = gr & 127;
        const float* yrow = Y + (size_t)(b0 + tile) * 1024 + j * 8;
        float sq = 0.f;
        int base = tile * 1152 + (j & 3) * 256 + (j >> 2) * 4;
        #pragma unroll
        for (int k = 0; k < 8; ++k) {
            float vv = yrow[k];
            sq = fmaf(vv, vv, sq);
            sy[base + (k >> 2) * 128 + (k & 3)] = vv;
        }
        sy[tile * 1152 + 1024 + (j & 3) * 32 + (j >> 2)] = sq * (-L2E);
    }

    // X: packed xs2 = +2*L2E*x ; nsqx = -L2E*|x|^2  ->  dot result = -L2E*d
    u64   xs2[4][4];
    float nsqx[4];
    {
        const float* xp = X + (size_t)a * 1024 + lane * 32;
        #pragma unroll
        for (int s = 0; s < 4; ++s) {
            float acc = 0.f;
            #pragma unroll
            for (int kp = 0; kp < 4; ++kp) {
                float f0 = xp[s * 8 + 2 * kp];
                float f1 = xp[s * 8 + 2 * kp + 1];
                acc = fmaf(f0, f0, fmaf(f1, f1, acc));
                xs2[s][kp] = pk2(f0 * (2.0f * L2E), f1 * (2.0f * L2E));
            }
            nsqx[s] = acc * (-L2E);
        }
    }
    __syncthreads();

    // DP state: mantissa e in [1,2), exponent q (int). BIG == q very negative.
    float e[2][4];
    int   q[2][4];
    #pragma unroll
    for (int s = 0; s < 4; ++s) {
        e[0][s] = 1.0f; e[1][s] = 1.0f;
        q[0][s] = BIGQ; q[1][s] = BIGQ;
    }

    // Y register pipeline: buffer (p)&3 holds row ja0(p) = p - 4*lane;
    // refilled at the END of each step, after slot 3 (its last reader) is done.
    u64   yp2[4][4];
    float nyq[4];
    #pragma unroll
    for (int b = 0; b < 4; ++b) {
        nyq[b] = 0.f;
        #pragma unroll
        for (int kp = 0; kp < 4; ++kp) yp2[b][kp] = 0ull;
    }

    const int lane4 = lane * 4;

    // prologue: buffer 0 <- row ja0(p=0) = -lane4 (wrapped; real only for lane 0)
    {
        unsigned jb = (unsigned)(-lane4) & 255u;
        int t   = (int)(jb >> 7) * 1152;
        int off = (int)((jb >> 2) & 31u);
        int A   = t + (int)(jb & 3u) * 256 + off * 4;
        float4 c0 = *reinterpret_cast<const float4*>(&sy[A]);
        float4 c1 = *reinterpret_cast<const float4*>(&sy[A + 128]);
        yp2[0][0] = pk2(c0.x, c0.y); yp2[0][1] = pk2(c0.z, c0.w);
        yp2[0][2] = pk2(c1.x, c1.y); yp2[0][3] = pk2(c1.z, c1.w);
        nyq[0] = sy[t + 1024 + (int)(jb & 3u) * 32 + off];
    }

    float shPe = 1.0f;
    int   shPq = BIGQ;
    const int outA = a * 16 + b0;

    for (int p0 = 0; p0 < 384; p0 += 4) {
        const int j0      = p0 - lane4;
        const unsigned jc = (unsigned)j0 & 255u;
        const unsigned jn = (unsigned)(j0 + 4) & 255u;
        const int tOff0   = (int)(jc >> 7) * 1152;
        const int m0      = (int)((jc >> 2) & 31u);
        const int baseY0  = tOff0 + m0 * 4;
        const int qb0     = tOff0 + 1024 + m0;
        const int tOff1   = (int)(jn >> 7) * 1152;
        const int m1      = (int)((jn >> 2) & 31u);
        const int baseY1  = tOff1 + m1 * 4;
        const int qb1     = tOff1 + 1024 + m1;
        const bool bj0    = ((jc & 127u) == 0u);   // j==0 boundary fires only at cells s==u

        #pragma unroll
        for (int u = 0; u < 4; ++u) {
            const int wIdx = u & 1;
            const int rIdx = wIdx ^ 1;

            const float sh1e = __shfl_up_sync(0xffffffffu, e[rIdx][3], 1);
            const int   sh1q = __shfl_up_sync(0xffffffffu, q[rIdx][3], 1);

            // reverse slot order: slot s reads (e,q)[wIdx][s-1] (prev2) before slot s-1 writes
            #pragma unroll
            for (int s = 3; s >= 0; --s) {
                float eu, el, ed;
                int   qu, ql, qd;
                if (s == 0) {
                    eu = sh1e;  qu = (lane == 0) ? BIGQ : sh1q;
                    if (u == 0) {
                        el = e[rIdx][0];  ql = bj0 ? BIGQ : q[rIdx][0];
                        if (lane == 0) { ed = 1.0f;  qd = bj0 ? 0 : BIGQ; }   // corner seed
                        else           { ed = shPe;  qd = bj0 ? BIGQ : shPq; }
                    } else {
                        el = e[rIdx][0];  ql = q[rIdx][0];
                        ed = shPe;        qd = (lane == 0) ? BIGQ : shPq;
                    }
                } else {
                    eu = e[rIdx][s - 1];  qu = q[rIdx][s - 1];
                    if (s == u) {
                        el = e[rIdx][s];      ql = bj0 ? BIGQ : q[rIdx][s];
                        ed = e[wIdx][s - 1];  qd = bj0 ? BIGQ : q[wIdx][s - 1];
                    } else {
                        el = e[rIdx][s];      ql = q[rIdx][s];
                        ed = e[wIdx][s - 1];  qd = q[wIdx][s - 1];
                    }
                }

                // weight-domain softmin: align exponents to max q, add mantissas.
                // qm owner contributes its e >= 1  =>  sum in [1,6); clamp makes
                // far terms (incl. BIGQ masks) vanish exactly enough (<= 2^-126).
                int qm = max(max(qu, ql), qd);
                float sum = (scl_(eu, qu - qm) + scl_(el, ql - qm)) + scl_(ed, qd - qm);

                // distance exponent dn = -L2E*|x-y|^2 (neighbor-independent -> off-chain MUFU)
                u64 acc2 = pk2(nsqx[s], nyq[(u - s) & 3]);
                #pragma unroll
                for (int kp = 0; kp < 4; ++kp)
                    acc2 = fma2(xs2[s][kp], yp2[(u - s) & 3][kp], acc2);
                float lo, hi; upk2(lo, hi, acc2);
                float w = sum * ex2f_(lo + hi);     // w in [2^-123, 6): always normal

                // exact exponent/mantissa split
                unsigned wb = __float_as_uint(w);
                q[wIdx][s] = qm + (int)(wb >> 23) - 127;
                e[wIdx][s] = __uint_as_float((wb & 0x007FFFFFu) | 0x3F800000u);
            }

            // refill buffer (u+1)&3 with row j0+u+1 AFTER its last reader (slot 3) is done
            {
                const int A = (u < 3) ? (baseY0 + (u + 1) * 256) : baseY1;
                const int b = (u + 1) & 3;
                float4 c0 = *reinterpret_cast<const float4*>(&sy[A]);
                float4 c1 = *reinterpret_cast<const float4*>(&sy[A + 128]);
                yp2[b][0] = pk2(c0.x, c0.y); yp2[b][1] = pk2(c0.z, c0.w);
                yp2[b][2] = pk2(c1.x, c1.y); yp2[b][3] = pk2(c1.z, c1.w);
                nyq[b] = (u < 3) ? sy[qb0 + (u + 1) * 32] : sy[qb1];
            }

            // harvest: V = -LN2 * (q + lg2(e));  pair A at p=254, pair B at p=382
            if (u == 2 && lane == 31) {
                if (p0 == 252) out[outA]     = -((float)q[0][3] + lg2f_(e[0][3])) * LN2;
                if (p0 == 380) out[outA + 1] = -((float)q[0][3] + lg2f_(e[0][3])) * LN2;
            }

            shPe = sh1e;
            shPq = sh1q;
        }
    }
}

extern "C" void kernel_launch(void* const* d_in, const int* in_sizes, int n_in,
                              void* d_out, int out_size)
{
    const float* X = (const float*)d_in[0];
    const float* Y = (const float*)d_in[1];
    if (n_in >= 2 && in_sizes[0] < in_sizes[1]) {
        const float* t = X; X = Y; Y = t;
    }
    float* out = (float*)d_out;

    sdtw_kernel<<<256, 128>>>(X, Y, out);
}

// round 8
// speedup vs baseline: 1.2478x; 1.1177x over previous
#include <cuda_runtime.h>

#define L2E  1.4426950408889634f
#define LN2  0.6931471805599453f
#define BIGQ (-(1 << 27))

typedef unsigned long long u64;

__device__ __forceinline__ float ex2f_(float x){ float r; asm("ex2.approx.f32 %0, %1;" : "=f"(r) : "f"(x)); return r; }
__device__ __forceinline__ float lg2f_(float x){ float r; asm("lg2.approx.f32 %0, %1;" : "=f"(r) : "f"(x)); return r; }
__device__ __forceinline__ u64 pk2(float lo, float hi){ u64 r; asm("mov.b64 %0,{%1,%2};" : "=l"(r) : "f"(lo), "f"(hi)); return r; }
__device__ __forceinline__ void upk2(float& lo, float& hi, u64 v){ asm("mov.b64 {%0,%1},%2;" : "=f"(lo), "=f"(hi) : "l"(v)); }
__device__ __forceinline__ u64 fma2(u64 a, u64 b, u64 c){ u64 r; asm("fma.rn.f32x2 %0,%1,%2,%3;" : "=l"(r) : "l"(a), "l"(b), "l"(c)); return r; }

// exact e * 2^max(dq, -126), e in [1,2), dq <= 0  (pure ALU, no MUFU)
__device__ __forceinline__ float scl_(float e, int dq){
    int d = dq < -126 ? -126 : dq;
    return __uint_as_float(__float_as_uint(e) + ((unsigned)d << 23));
}

// One warp = FOUR (a,b) pairs chained in anti-phase (+128 steps each), 4 rows/thread.
// 640 steps for 4 pairs (80% wavefront density). 512 warps total -> exactly
// 1 warp per SMSP on the loaded SMs (no 2-block straggler SMs).
// DP carried in weight domain w = e * 2^q (e float in [1,2), q int32):
// softmin = exponent-aligned add (pure ALU on the carried chain); the single
// ex2 per cell takes the neighbor-independent distance term.
__global__ __launch_bounds__(128)
void sdtw_kernel(const float* __restrict__ X, const float* __restrict__ Y,
                 float* __restrict__ out)
{
    // 4 tiles; row j of tile t: sy[t*1152 + (j&3)*256 + c*128 + (j>>2)*4 + k]
    // nsqy = -L2E*|Y[j]|^2 at sy[t*1152 + 1024 + (j&3)*32 + (j>>2)]
    __shared__ __align__(16) float sy[4 * 1152];

    const int tid  = threadIdx.x;
    const int lane = tid & 31;
    const int wid  = tid >> 5;

    const int b0 = (blockIdx.x & 3) * 4;          // 4 consecutive b per warp-chain
    const int a  = (blockIdx.x >> 2) * 4 + wid;

    for (int rep = 0; rep < 4; ++rep) {
        int gr   = tid + rep * 128;               // 0..511
        int tile = gr >> 7;
        int j    = gr & 127;
        const float* yrow = Y + (size_t)(b0 + tile) * 1024 + j * 8;
        float sq = 0.f;
        int base = tile * 1152 + (j & 3) * 256 + (j >> 2) * 4;
        #pragma unroll
        for (int k = 0; k < 8; ++k) {
            float vv = yrow[k];
            sq = fmaf(vv, vv, sq);
            sy[base + (k >> 2) * 128 + (k & 3)] = vv;
        }
        sy[tile * 1152 + 1024 + (j & 3) * 32 + (j >> 2)] = sq * (-L2E);
    }

    // X: packed xs2 = +2*L2E*x ; nsqx = -L2E*|x|^2  ->  dot result = -L2E*d
    u64   xs2[4][4];
    float nsqx[4];
    {
        const float* xp = X + (size_t)a * 1024 + lane * 32;
        #pragma unroll
        for (int s = 0; s < 4; ++s) {
            float acc = 0.f;
            #pragma unroll
            for (int kp = 0; kp < 4; ++kp) {
                float f0 = xp[s * 8 + 2 * kp];
                float f1 = xp[s * 8 + 2 * kp + 1];
                acc = fmaf(f0, f0, fmaf(f1, f1, acc));
                xs2[s][kp] = pk2(f0 * (2.0f * L2E), f1 * (2.0f * L2E));
            }
            nsqx[s] = acc * (-L2E);
        }
    }
    __syncthreads();

    // DP state: mantissa e in [1,2), exponent q (int). Dead/masked == q very negative.
    float e[2][4];
    int   q[2][4];
    #pragma unroll
    for (int s = 0; s < 4; ++s) {
        e[0][s] = 1.0f; e[1][s] = 1.0f;
        q[0][s] = BIGQ; q[1][s] = BIGQ;
    }

    // Y register pipeline: buffer (p)&3 holds row ja0(p) = p - 4*lane;
    // refilled at the END of each step, after slot 3 (its last reader) is done.
    u64   yp2[4][4];
    float nyq[4];
    #pragma unroll
    for (int b = 0; b < 4; ++b) {
        nyq[b] = 0.f;
        #pragma unroll
        for (int kp = 0; kp < 4; ++kp) yp2[b][kp] = 0ull;
    }

    const int lane4 = lane * 4;

    // prologue: buffer 0 <- row ja0(p=0) = -lane4 (wrapped; real only for lane 0)
    {
        unsigned jb = (unsigned)(-lane4) & 511u;
        int t   = (int)(jb >> 7) * 1152;
        int off = (int)((jb >> 2) & 31u);
        int A   = t + (int)(jb & 3u) * 256 + off * 4;
        float4 c0 = *reinterpret_cast<const float4*>(&sy[A]);
        float4 c1 = *reinterpret_cast<const float4*>(&sy[A + 128]);
        yp2[0][0] = pk2(c0.x, c0.y); yp2[0][1] = pk2(c0.z, c0.w);
        yp2[0][2] = pk2(c1.x, c1.y); yp2[0][3] = pk2(c1.z, c1.w);
        nyq[0] = sy[t + 1024 + (int)(jb & 3u) * 32 + off];
    }

    float shPe = 1.0f;
    int   shPq = BIGQ;
    const int outA = a * 16 + b0;

    for (int p0 = 0; p0 < 640; p0 += 4) {
        const int j0      = p0 - lane4;
        const unsigned jc = (unsigned)j0 & 511u;
        const unsigned jn = (unsigned)(j0 + 4) & 511u;
        const int tOff0   = (int)(jc >> 7) * 1152;
        const int m0      = (int)((jc >> 2) & 31u);
        const int baseY0  = tOff0 + m0 * 4;
        const int qb0     = tOff0 + 1024 + m0;
        const int tOff1   = (int)(jn >> 7) * 1152;
        const int m1      = (int)((jn >> 2) & 31u);
        const int baseY1  = tOff1 + m1 * 4;
        const int qb1     = tOff1 + 1024 + m1;
        const bool bj0    = ((jc & 127u) == 0u);   // per-pair j==0 boundary: fires only at s==u

        #pragma unroll
        for (int u = 0; u < 4; ++u) {
            const int wIdx = u & 1;
            const int rIdx = wIdx ^ 1;

            const float sh1e = __shfl_up_sync(0xffffffffu, e[rIdx][3], 1);
            const int   sh1q = __shfl_up_sync(0xffffffffu, q[rIdx][3], 1);

            // reverse slot order: slot s reads (e,q)[wIdx][s-1] (prev2) before slot s-1 writes
            #pragma unroll
            for (int s = 3; s >= 0; --s) {
                float eu, el, ed;
                int   qu, ql, qd;
                if (s == 0) {
                    eu = sh1e;  qu = (lane == 0) ? BIGQ : sh1q;
                    if (u == 0) {
                        el = e[rIdx][0];  ql = bj0 ? BIGQ : q[rIdx][0];
                        if (lane == 0) { ed = 1.0f;  qd = bj0 ? 0 : BIGQ; }   // corner seed of each pair
                        else           { ed = shPe;  qd = bj0 ? BIGQ : shPq; }
                    } else {
                        el = e[rIdx][0];  ql = q[rIdx][0];
                        ed = shPe;        qd = (lane == 0) ? BIGQ : shPq;
                    }
                } else {
                    eu = e[rIdx][s - 1];  qu = q[rIdx][s - 1];
                    if (s == u) {
                        el = e[rIdx][s];      ql = bj0 ? BIGQ : q[rIdx][s];
                        ed = e[wIdx][s - 1];  qd = bj0 ? BIGQ : q[wIdx][s - 1];
                    } else {
                        el = e[rIdx][s];      ql = q[rIdx][s];
                        ed = e[wIdx][s - 1];  qd = q[wIdx][s - 1];
                    }
                }

                // weight-domain softmin: align exponents to max q, add mantissas.
                int qm = max(max(qu, ql), qd);
                float sum = (scl_(eu, qu - qm) + scl_(el, ql - qm)) + scl_(ed, qd - qm);

                // distance exponent -L2E*|x-y|^2 (neighbor-independent MUFU)
                u64 acc2 = pk2(nsqx[s], nyq[(u - s) & 3]);
                #pragma unroll
                for (int kp = 0; kp < 4; ++kp)
                    acc2 = fma2(xs2[s][kp], yp2[(u - s) & 3][kp], acc2);
                float lo, hi; upk2(lo, hi, acc2);
                float w = sum * ex2f_(lo + hi);     // w in [2^-123, 6): always a normal float

                // exact exponent/mantissa split
                unsigned wb = __float_as_uint(w);
                q[wIdx][s] = qm + (int)(wb >> 23) - 127;
                e[wIdx][s] = __uint_as_float((wb & 0x007FFFFFu) | 0x3F800000u);
            }

            // refill buffer (u+1)&3 with row j0+u+1 AFTER its last reader (slot 3) is done
            {
                const int A = (u < 3) ? (baseY0 + (u + 1) * 256) : baseY1;
                const int b = (u + 1) & 3;
                float4 c0 = *reinterpret_cast<const float4*>(&sy[A]);
                float4 c1 = *reinterpret_cast<const float4*>(&sy[A + 128]);
                yp2[b][0] = pk2(c0.x, c0.y); yp2[b][1] = pk2(c0.z, c0.w);
                yp2[b][2] = pk2(c1.x, c1.y); yp2[b][3] = pk2(c1.z, c1.w);
                nyq[b] = (u < 3) ? sy[qb0 + (u + 1) * 32] : sy[qb1];
            }

            // harvest pair k at p = 128k + 254 (p0 = 128k + 252, u = 2)
            if (u == 2 && lane == 31 && (p0 & 127) == 124 && p0 >= 252) {
                int k = (p0 - 252) >> 7;
                out[outA + k] = -((float)q[0][3] + lg2f_(e[0][3])) * LN2;
            }

            shPe = sh1e;
            shPq = sh1q;
        }
    }
}

extern "C" void kernel_launch(void* const* d_in, const int* in_sizes, int n_in,
                              void* d_out, int out_size)
{
    const float* X = (const float*)d_in[0];
    const float* Y = (const float*)d_in[1];
    if (n_in >= 2 && in_sizes[0] < in_sizes[1]) {
        const float* t = X; X = Y; Y = t;
    }
    float* out = (float*)d_out;

    // 128 blocks x 128 threads: block = 4 a-values x one b-quad; warp = 4 chained pairs.
    // <=1 block per SM -> exactly 1 warp per SMSP, uniform load.
    sdtw_kernel<<<128, 128>>>(X, Y, out);
}